// round 4
// baseline (speedup 1.0000x reference)
#include <cuda_runtime.h>

// Problem constants (fixed by the reference setup_inputs)
#define BB 4
#define TT 4096
#define CCH 1024
#define HH 64

// Scratch for projected q, k, v: [B*T, H] each (4 MB apiece) — static device
// arrays, no allocation.
__device__ float g_q[BB * TT * HH];
__device__ float g_k[BB * TT * HH];
__device__ float g_v[BB * TT * HH];

// ---------------------------------------------------------------------------
// Kernel 1: fused QKV projection.
// One block computes a [64 x 192] output tile (64 rows of x, 192 = 3*H cols
// spanning q|k|v), looping over K=1024 in chunks of 32 held in smem.
// 256 threads, thread (ty,tx) owns a 4x12 register microtile.
// ---------------------------------------------------------------------------
__global__ __launch_bounds__(256)
void qkv_proj(const float* __restrict__ x, const float* __restrict__ Wq,
              const float* __restrict__ Wk, const float* __restrict__ Wv)
{
    __shared__ float xs[64 * 32];    // x chunk  [64 rows][32 k]
    __shared__ float ws[32 * 192];   // W chunk  [32 k][192 cols]

    const int tid  = threadIdx.x;
    const int row0 = blockIdx.x * 64;
    const int ty   = tid >> 4;   // 0..15 -> rows ty*4..+3
    const int tx   = tid & 15;   // 0..15 -> cols tx*12..+11

    float acc[4][12];
#pragma unroll
    for (int r = 0; r < 4; r++)
#pragma unroll
        for (int j = 0; j < 12; j++) acc[r][j] = 0.f;

    for (int kk = 0; kk < CCH; kk += 32) {
        __syncthreads();   // previous chunk's reads complete
        // load x chunk: 512 float4
#pragma unroll
        for (int l = 0; l < 2; l++) {
            int idx = tid + l * 256;
            int r = idx >> 3, c4 = idx & 7;
            *(float4*)&xs[r * 32 + c4 * 4] =
                *(const float4*)&x[(size_t)(row0 + r) * CCH + kk + c4 * 4];
        }
        // load W chunk: 32*48 float4 (q|k|v concatenated along columns)
#pragma unroll
        for (int l = 0; l < 6; l++) {
            int idx = tid + l * 256;
            int kr = idx / 48;
            int c  = (idx % 48) * 4;
            const float* Wsrc = (c < 64) ? Wq : ((c < 128) ? Wk : Wv);
            *(float4*)&ws[kr * 192 + c] =
                *(const float4*)&Wsrc[(size_t)(kk + kr) * HH + (c & 63)];
        }
        __syncthreads();

#pragma unroll 8
        for (int k = 0; k < 32; k++) {
            float a[4];
#pragma unroll
            for (int r = 0; r < 4; r++) a[r] = xs[(ty * 4 + r) * 32 + k];
            float4 b0 = *(float4*)&ws[k * 192 + tx * 12];
            float4 b1 = *(float4*)&ws[k * 192 + tx * 12 + 4];
            float4 b2 = *(float4*)&ws[k * 192 + tx * 12 + 8];
            float bb[12] = {b0.x, b0.y, b0.z, b0.w,
                            b1.x, b1.y, b1.z, b1.w,
                            b2.x, b2.y, b2.z, b2.w};
#pragma unroll
            for (int r = 0; r < 4; r++)
#pragma unroll
                for (int j = 0; j < 12; j++)
                    acc[r][j] = fmaf(a[r], bb[j], acc[r][j]);
        }
    }

    // scatter to g_q / g_k / g_v
#pragma unroll
    for (int r = 0; r < 4; r++) {
        int row = row0 + ty * 4 + r;
#pragma unroll
        for (int j = 0; j < 12; j++) {
            int c = tx * 12 + j;
            float* dst = (c < 64) ? g_q : ((c < 128) ? g_k : g_v);
            dst[(size_t)row * HH + (c & 63)] = acc[r][j];
        }
    }
}

// ---------------------------------------------------------------------------
// Kernel 2: causal flash attention, fp32.
// Block = (batch b, 64-row query tile i). 256 threads; thread (ty,tx) owns a
// 4x4 microtile of S (rows ty*4.., cols tx*4..) and of O (rows ty*4.., head
// dims tx*4..). Row softmax stats live in registers, replicated across the 16
// tx-threads of each row group via 16-lane shuffles.
// Smem: Qs [r][h], KtPs dual-use (K transposed [h][c] for the S GEMM, then
// overwritten with P [r][c] for the PV GEMM), Vs [c][h].
// All hot-loop smem reads are common-row (stride-free) or broadcast.
// Exactly 48 KB static smem.
// ---------------------------------------------------------------------------
__global__ __launch_bounds__(256)
void attn(float* __restrict__ out)
{
    __shared__ float Qs[64 * 64];
    __shared__ float KtPs[64 * 64];
    __shared__ float Vs[64 * 64];

    const int tid  = threadIdx.x;
    const int ty   = tid >> 4;
    const int tx   = tid & 15;
    const int iblk = (int)gridDim.x - 1 - (int)blockIdx.x;  // heavy tiles first
    const int b    = blockIdx.y;

    const float* qg = g_q + (size_t)b * TT * HH;
    const float* kg = g_k + (size_t)b * TT * HH;
    const float* vg = g_v + (size_t)b * TT * HH;

    // load Q tile [64][64]
#pragma unroll
    for (int l = 0; l < 4; l++) {
        int idx = tid + l * 256;
        int r = idx >> 4, c4 = idx & 15;
        *(float4*)&Qs[r * 64 + c4 * 4] =
            *(const float4*)&qg[(size_t)(iblk * 64 + r) * HH + c4 * 4];
    }

    float accO[4][4];
    float mrun[4], lrun[4];
#pragma unroll
    for (int r = 0; r < 4; r++) {
        mrun[r] = -1e30f;
        lrun[r] = 0.f;
#pragma unroll
        for (int c = 0; c < 4; c++) accO[r][c] = 0.f;
    }

    for (int j = 0; j <= iblk; j++) {
        const int jc0 = j * 64;
        __syncthreads();   // previous tile's PV reads done; Q load visible

        // K tile, transposed into KtPs[h*64 + c]
        {
            int cbase = tid >> 4;   // 0..15
            int h4    = tid & 15;   // 0..15 (float4 index along h)
#pragma unroll
            for (int l = 0; l < 4; l++) {
                int c = cbase + 16 * l;
                float4 kv = *(const float4*)&kg[(size_t)(jc0 + c) * HH + h4 * 4];
                KtPs[(h4 * 4 + 0) * 64 + c] = kv.x;
                KtPs[(h4 * 4 + 1) * 64 + c] = kv.y;
                KtPs[(h4 * 4 + 2) * 64 + c] = kv.z;
                KtPs[(h4 * 4 + 3) * 64 + c] = kv.w;
            }
        }
        // V tile [c][h], natural layout
#pragma unroll
        for (int l = 0; l < 4; l++) {
            int idx = tid + l * 256;
            int r = idx >> 4, c4 = idx & 15;
            *(float4*)&Vs[r * 64 + c4 * 4] =
                *(const float4*)&vg[(size_t)(jc0 + r) * HH + c4 * 4];
        }
        __syncthreads();

        // ---- S = Q K^T ----
        float accS[4][4];
#pragma unroll
        for (int r = 0; r < 4; r++)
#pragma unroll
            for (int c = 0; c < 4; c++) accS[r][c] = 0.f;

#pragma unroll 4
        for (int h = 0; h < 64; h += 4) {
            float4 k0 = *(float4*)&KtPs[(h + 0) * 64 + tx * 4];
            float4 k1 = *(float4*)&KtPs[(h + 1) * 64 + tx * 4];
            float4 k2 = *(float4*)&KtPs[(h + 2) * 64 + tx * 4];
            float4 k3 = *(float4*)&KtPs[(h + 3) * 64 + tx * 4];
#pragma unroll
            for (int r = 0; r < 4; r++) {
                float4 qv = *(float4*)&Qs[(ty * 4 + r) * 64 + h];
                accS[r][0] = fmaf(qv.x, k0.x, accS[r][0]);
                accS[r][1] = fmaf(qv.x, k0.y, accS[r][1]);
                accS[r][2] = fmaf(qv.x, k0.z, accS[r][2]);
                accS[r][3] = fmaf(qv.x, k0.w, accS[r][3]);
                accS[r][0] = fmaf(qv.y, k1.x, accS[r][0]);
                accS[r][1] = fmaf(qv.y, k1.y, accS[r][1]);
                accS[r][2] = fmaf(qv.y, k1.z, accS[r][2]);
                accS[r][3] = fmaf(qv.y, k1.w, accS[r][3]);
                accS[r][0] = fmaf(qv.z, k2.x, accS[r][0]);
                accS[r][1] = fmaf(qv.z, k2.y, accS[r][1]);
                accS[r][2] = fmaf(qv.z, k2.z, accS[r][2]);
                accS[r][3] = fmaf(qv.z, k2.w, accS[r][3]);
                accS[r][0] = fmaf(qv.w, k3.x, accS[r][0]);
                accS[r][1] = fmaf(qv.w, k3.y, accS[r][1]);
                accS[r][2] = fmaf(qv.w, k3.z, accS[r][2]);
                accS[r][3] = fmaf(qv.w, k3.w, accS[r][3]);
            }
        }

        // ---- online softmax ----  scale = 1/sqrt(C) = 1/32 (reference scales by C**0.5)
        const bool diag = (j == iblk);
        float p[4][4];
#pragma unroll
        for (int r = 0; r < 4; r++) {
            const int grow = iblk * 64 + ty * 4 + r;
            float mloc = -1e30f;
#pragma unroll
            for (int c = 0; c < 4; c++) {
                float s = accS[r][c] * 0.03125f;
                if (diag && (jc0 + tx * 4 + c > grow)) s = -1e30f;
                accS[r][c] = s;
                mloc = fmaxf(mloc, s);
            }
            // reduce across the 16 tx-threads (lanes 0-15 / 16-31 stay in-group)
            mloc = fmaxf(mloc, __shfl_xor_sync(0xffffffffu, mloc, 8));
            mloc = fmaxf(mloc, __shfl_xor_sync(0xffffffffu, mloc, 4));
            mloc = fmaxf(mloc, __shfl_xor_sync(0xffffffffu, mloc, 2));
            mloc = fmaxf(mloc, __shfl_xor_sync(0xffffffffu, mloc, 1));
            float mnew  = fmaxf(mrun[r], mloc);
            float alpha = __expf(mrun[r] - mnew);
            mrun[r] = mnew;
            float psum = 0.f;
#pragma unroll
            for (int c = 0; c < 4; c++) {
                float pe = __expf(accS[r][c] - mnew);
                p[r][c] = pe;
                psum += pe;
            }
            psum += __shfl_xor_sync(0xffffffffu, psum, 8);
            psum += __shfl_xor_sync(0xffffffffu, psum, 4);
            psum += __shfl_xor_sync(0xffffffffu, psum, 2);
            psum += __shfl_xor_sync(0xffffffffu, psum, 1);
            lrun[r] = lrun[r] * alpha + psum;
#pragma unroll
            for (int c = 0; c < 4; c++) accO[r][c] *= alpha;
        }

        __syncthreads();   // all S-phase reads of KtPs done
        // write P over the K buffer: Ps[r*64 + c]
#pragma unroll
        for (int r = 0; r < 4; r++) {
            float4 pv = make_float4(p[r][0], p[r][1], p[r][2], p[r][3]);
            *(float4*)&KtPs[(ty * 4 + r) * 64 + tx * 4] = pv;
        }
        __syncthreads();

        // ---- O += P V ----
#pragma unroll 4
        for (int c = 0; c < 64; c += 4) {
            float4 v0 = *(float4*)&Vs[(c + 0) * 64 + tx * 4];
            float4 v1 = *(float4*)&Vs[(c + 1) * 64 + tx * 4];
            float4 v2 = *(float4*)&Vs[(c + 2) * 64 + tx * 4];
            float4 v3 = *(float4*)&Vs[(c + 3) * 64 + tx * 4];
#pragma unroll
            for (int r = 0; r < 4; r++) {
                float4 pv = *(float4*)&KtPs[(ty * 4 + r) * 64 + c];
                accO[r][0] = fmaf(pv.x, v0.x, accO[r][0]);
                accO[r][1] = fmaf(pv.x, v0.y, accO[r][1]);
                accO[r][2] = fmaf(pv.x, v0.z, accO[r][2]);
                accO[r][3] = fmaf(pv.x, v0.w, accO[r][3]);
                accO[r][0] = fmaf(pv.y, v1.x, accO[r][0]);
                accO[r][1] = fmaf(pv.y, v1.y, accO[r][1]);
                accO[r][2] = fmaf(pv.y, v1.z, accO[r][2]);
                accO[r][3] = fmaf(pv.y, v1.w, accO[r][3]);
                accO[r][0] = fmaf(pv.z, v2.x, accO[r][0]);
                accO[r][1] = fmaf(pv.z, v2.y, accO[r][1]);
                accO[r][2] = fmaf(pv.z, v2.z, accO[r][2]);
                accO[r][3] = fmaf(pv.z, v2.w, accO[r][3]);
                accO[r][0] = fmaf(pv.w, v3.x, accO[r][0]);
                accO[r][1] = fmaf(pv.w, v3.y, accO[r][1]);
                accO[r][2] = fmaf(pv.w, v3.z, accO[r][2]);
                accO[r][3] = fmaf(pv.w, v3.w, accO[r][3]);
            }
        }
    }

    // normalize and write out [B,T,H]
#pragma unroll
    for (int r = 0; r < 4; r++) {
        float inv = 1.f / lrun[r];
        float4 o = make_float4(accO[r][0] * inv, accO[r][1] * inv,
                               accO[r][2] * inv, accO[r][3] * inv);
        *(float4*)&out[(size_t)(b * TT + iblk * 64 + ty * 4 + r) * HH + tx * 4] = o;
    }
}

// ---------------------------------------------------------------------------
extern "C" void kernel_launch(void* const* d_in, const int* in_sizes, int n_in,
                              void* d_out, int out_size)
{
    (void)in_sizes; (void)n_in; (void)out_size;
    const float* x  = (const float*)d_in[0];
    const float* Wq = (const float*)d_in[1];
    const float* Wk = (const float*)d_in[2];
    const float* Wv = (const float*)d_in[3];
    float* out = (float*)d_out;

    qkv_proj<<<(BB * TT) / 64, 256>>>(x, Wq, Wk, Wv);
    attn<<<dim3(TT / 64, BB), 256>>>(out);
}